// round 7
// baseline (speedup 1.0000x reference)
#include <cuda_runtime.h>
#include <cuda_bf16.h>

// Contour_to_mask: winding-number mask, 512x512 px, 128 contour points.
// Reference: sum_n tanh(K*cross_n) * acos(clip(cos_n,-1+eps,1-eps)) / 2pi, clipped [0,1].
// theta = acos(dot/(|d||r|)) = atan2(|cross|, dot); the clamp maps exactly to
// theta in [acos(1-eps), pi-acos(1-eps)].
// cross_j = w_j + py*ex_j - px*ey_j,  dot_j = d_j + px(px-sx_j) + py(py-sy_j):
// px is block-constant -> folded into smem per block; per-iter front-end is
// 3 packed f32x2 ops + 2 LDS.128. All scaled by K (ratio/sign invariant).
// 2048 blocks x 64 threads for balance; 2 px/thread packed.

#define MSIZE 512
#define NPTS  128
#define KCONST 100000.0f
#define INV2PI 0.15915494309189535f
#define PI_2F  1.57079632679489662f
#define THMIN  0.0044721364f            /* acos(1 - 1e-5) */
#define THMAX  3.1371205172f            /* pi - acos(1 - 1e-5) */

typedef unsigned long long u64;

__device__ __forceinline__ u64 pk2(float lo, float hi) {
    u64 r; asm("mov.b64 %0,{%1,%2};" : "=l"(r) : "f"(lo), "f"(hi)); return r;
}
__device__ __forceinline__ void upk2(u64 v, float& lo, float& hi) {
    asm("mov.b64 {%0,%1},%2;" : "=f"(lo), "=f"(hi) : "l"(v));
}
__device__ __forceinline__ u64 mul2(u64 a, u64 b) {
    u64 r; asm("mul.rn.f32x2 %0,%1,%2;" : "=l"(r) : "l"(a), "l"(b)); return r;
}
__device__ __forceinline__ u64 add2(u64 a, u64 b) {
    u64 r; asm("add.rn.f32x2 %0,%1,%2;" : "=l"(r) : "l"(a), "l"(b)); return r;
}
__device__ __forceinline__ u64 fma2(u64 a, u64 b, u64 c) {
    u64 r; asm("fma.rn.f32x2 %0,%1,%2,%3;" : "=l"(r) : "l"(a), "l"(b), "l"(c)); return r;
}
__device__ __forceinline__ float ftanh(float x) {
    float r; asm("tanh.approx.f32 %0,%1;" : "=f"(r) : "f"(x)); return r;
}
__device__ __forceinline__ float frcp(float x) {
    float r; asm("rcp.approx.f32 %0,%1;" : "=f"(r) : "f"(x)); return r;
}
// +-1.0f carrying the sign of x: one LOP3
__device__ __forceinline__ float sgn1(float x) {
    return __int_as_float(0x3f800000 | (__float_as_int(x) & 0x80000000));
}

__global__ void __launch_bounds__(64)
contour_mask_kernel(const float* __restrict__ contour, float* __restrict__ out) {
    // per-edge, per-block constants, duplicated into lane pairs, 16B-grouped:
    // s[2j]   = (tK, tK, exK, exK)   tK = K*(w - px*ey), exK = K*ex
    // s[2j+1] = (UK, UK, -sy, -sy)   UK = K*(d + px*(px-sx))
    __shared__ float4 s[2 * NPTS];
    const int t = threadIdx.x;
    const int row = blockIdx.x >> 2;
    const float px = (float)row * (1.0f / (float)MSIZE);

    // 64 threads fill 128 edges: 2 each
    for (int e = t; e < NPTS; e += 64) {
        const float2 c0 = reinterpret_cast<const float2*>(contour)[e];
        const float2 c1 = reinterpret_cast<const float2*>(contour)[(e + 1) & (NPTS - 1)];
        const float w  = fmaf(c0.y, c1.x, -(c0.x * c1.y));  // cy0*cx1 - cx0*cy1
        const float ex = c0.x - c1.x;
        const float ey = c0.y - c1.y;
        const float d  = fmaf(c0.x, c1.x, c0.y * c1.y);
        const float sx = c0.x + c1.x;
        const float sy = c0.y + c1.y;
        const float tK  = KCONST * fmaf(-px, ey, w);
        const float exK = KCONST * ex;
        const float UK  = KCONST * fmaf(px, px - sx, d);
        s[2 * e]     = make_float4(tK, tK, exK, exK);
        s[2 * e + 1] = make_float4(UK, UK, -sy, -sy);
    }
    __syncthreads();

    const int col0 = ((blockIdx.x & 3) << 6) + t;   // 0..255
    const float py0 = (float)col0         * (1.0f / (float)MSIZE);
    const float py1 = (float)(col0 + 256) * (1.0f / (float)MSIZE);
    const u64 pyv  = pk2(py0, py1);
    const u64 Kpyv = pk2(KCONST * py0, KCONST * py1);

    // atan poly, A&S 4.4.47-class (|err| <= 1e-5 rad on [0,1]): atan(r) ~ r*P(r^2)
    const u64 A9 = pk2( 0.0208351f,  0.0208351f);
    const u64 A7 = pk2(-0.0851330f, -0.0851330f);
    const u64 A5 = pk2( 0.1801410f,  0.1801410f);
    const u64 A3 = pk2(-0.3302995f, -0.3302995f);
    const u64 A1 = pk2( 0.9998660f,  0.9998660f);

    const ulonglong2* sv = reinterpret_cast<const ulonglong2*>(s);  // LDS.128 each

    float sum0 = 0.0f, sum1 = 0.0f;

#pragma unroll 8
    for (int j = 0; j < NPTS; ++j) {
        const ulonglong2 q0 = sv[2 * j];       // .x = (tK,tK), .y = (exK,exK)
        const ulonglong2 q1 = sv[2 * j + 1];   // .x = (UK,UK), .y = (-sy,-sy)

        const u64 crv = fma2(pyv, q0.y, q0.x);           // K*cross
        const u64 pys = add2(pyv, q1.y);                 // py - sy
        const u64 dtv = fma2(Kpyv, pys, q1.x);           // K*dot

        float cr0, cr1, c0, c1;
        upk2(crv, cr0, cr1);
        upk2(dtv, c0, c1);

        const float a0 = fabsf(cr0), a1 = fabsf(cr1);
        const float b0 = fabsf(c0),  b1 = fabsf(c1);
        const float M0 = fmaxf(a0, b0), M1 = fmaxf(a1, b1);
        const float m0 = fminf(a0, b0), m1 = fminf(a1, b1);
        const float r0 = m0 * frcp(M0);
        const float r1 = m1 * frcp(M1);

        // packed odd poly: al = atan(r), r in [0,1]
        const u64 rv  = pk2(r0, r1);
        const u64 r2v = mul2(rv, rv);
        u64 pv = fma2(A9, r2v, A7);
        pv = fma2(pv, r2v, A5);
        pv = fma2(pv, r2v, A3);
        pv = fma2(pv, r2v, A1);
        const u64 av = mul2(pv, rv);
        float al0, al1;
        upk2(av, al0, al1);

        // v = atan(|cr|/|c|) mapped to [0,pi/2]; theta = pi/2 - sign(dot)*v
        const float h0 = PI_2F - al0;
        const float h1 = PI_2F - al1;
        const float v0 = (b0 > a0) ? h0 : al0;
        const float v1 = (b1 > a1) ? h1 : al1;
        float th0 = fmaf(sgn1(c0), -v0, PI_2F);
        float th1 = fmaf(sgn1(c1), -v1, PI_2F);

        // exact reference clamp: theta in [acos(1-eps), pi-acos(1-eps)]
        th0 = fminf(fmaxf(th0, THMIN), THMAX);
        th1 = fminf(fmaxf(th1, THMIN), THMAX);

        sum0 = fmaf(ftanh(cr0), th0, sum0);              // cr IS K*cross
        sum1 = fmaf(ftanh(cr1), th1, sum1);
    }

    const int base = row * MSIZE + col0;
    out[base]       = fminf(fmaxf(sum0 * INV2PI, 0.0f), 1.0f);
    out[base + 256] = fminf(fmaxf(sum1 * INV2PI, 0.0f), 1.0f);
}

extern "C" void kernel_launch(void* const* d_in, const int* in_sizes, int n_in,
                              void* d_out, int out_size) {
    const float* contour = (const float*)d_in[0];
    float* out = (float*)d_out;
    contour_mask_kernel<<<MSIZE * 4, 64>>>(contour, out);
}

// round 8
// speedup vs baseline: 1.0703x; 1.0703x over previous
#include <cuda_runtime.h>
#include <cuda_bf16.h>

// Contour_to_mask: winding-number mask, 512x512 px, 128 contour points.
// theta = acos(clip(cos,-1+eps,1-eps)) == clip(atan2(|cross|,dot), acos(1-eps), pi-acos(1-eps)),
// and since theta = pi/2 -+ v (v>=0), the clamp is exactly v = min(v, pi/2 - acos(1-eps)).
// cross_j = tK_j + py*exK_j, dot_j = UK_j + K*py*(py - sy_j) with px folded per block.
// 2 px/thread packed f32x2; TWO edge streams (j and j+64) interleaved per loop trip
// for 4 independent dependency chains (latency hiding); 2 MUFU/px (RCP + TANH).

#define MSIZE 512
#define NPTS  128
#define HALFE 64
#define KCONST 100000.0f
#define INV2PI 0.15915494309189535f
#define PI_2F  1.57079632679489662f
#define VMAX   1.5663241903f            /* pi/2 - acos(1 - 1e-5) */

typedef unsigned long long u64;

__device__ __forceinline__ u64 pk2(float lo, float hi) {
    u64 r; asm("mov.b64 %0,{%1,%2};" : "=l"(r) : "f"(lo), "f"(hi)); return r;
}
__device__ __forceinline__ void upk2(u64 v, float& lo, float& hi) {
    asm("mov.b64 {%0,%1},%2;" : "=f"(lo), "=f"(hi) : "l"(v));
}
__device__ __forceinline__ u64 mul2(u64 a, u64 b) {
    u64 r; asm("mul.rn.f32x2 %0,%1,%2;" : "=l"(r) : "l"(a), "l"(b)); return r;
}
__device__ __forceinline__ u64 add2(u64 a, u64 b) {
    u64 r; asm("add.rn.f32x2 %0,%1,%2;" : "=l"(r) : "l"(a), "l"(b)); return r;
}
__device__ __forceinline__ u64 fma2(u64 a, u64 b, u64 c) {
    u64 r; asm("fma.rn.f32x2 %0,%1,%2,%3;" : "=l"(r) : "l"(a), "l"(b), "l"(c)); return r;
}
__device__ __forceinline__ float ftanh(float x) {
    float r; asm("tanh.approx.f32 %0,%1;" : "=f"(r) : "f"(x)); return r;
}
__device__ __forceinline__ float frcp(float x) {
    float r; asm("rcp.approx.f32 %0,%1;" : "=f"(r) : "f"(x)); return r;
}
// +-1.0f carrying the sign of x: one LOP3
__device__ __forceinline__ float sgn1(float x) {
    return __int_as_float(0x3f800000 | (__float_as_int(x) & 0x80000000));
}

// atan poly coefficients (A&S 4.4.47-class, |err| <= 1e-5 rad on [0,1])
#define A9v pk2( 0.0208351f,  0.0208351f)
#define A7v pk2(-0.0851330f, -0.0851330f)
#define A5v pk2( 0.1801410f,  0.1801410f)
#define A3v pk2(-0.3302995f, -0.3302995f)
#define A1v pk2( 0.9998660f,  0.9998660f)

struct Edge2 { u64 tK, exK, UK, nsy; };

// one packed (2-pixel) edge evaluation; accumulates into sum0/sum1
__device__ __forceinline__ void edge_eval(
    const ulonglong2 q0, const ulonglong2 q1,
    const u64 pyv, const u64 Kpyv,
    const u64 A9, const u64 A7, const u64 A5, const u64 A3, const u64 A1,
    float& sum0, float& sum1)
{
    const u64 crv = fma2(pyv, q0.y, q0.x);            // K*cross
    const u64 pys = add2(pyv, q1.y);                  // py - sy
    const u64 dtv = fma2(Kpyv, pys, q1.x);            // K*dot

    float cr0, cr1, c0, c1;
    upk2(crv, cr0, cr1);
    upk2(dtv, c0, c1);

    const float a0 = fabsf(cr0), a1 = fabsf(cr1);
    const float b0 = fabsf(c0),  b1 = fabsf(c1);
    const float M0 = fmaxf(a0, b0), M1 = fmaxf(a1, b1);
    const float m0 = fminf(a0, b0), m1 = fminf(a1, b1);
    const float r0 = m0 * frcp(M0);
    const float r1 = m1 * frcp(M1);

    const u64 rv  = pk2(r0, r1);
    const u64 r2v = mul2(rv, rv);
    u64 pv = fma2(A9, r2v, A7);
    pv = fma2(pv, r2v, A5);
    pv = fma2(pv, r2v, A3);
    pv = fma2(pv, r2v, A1);
    const u64 av = mul2(pv, rv);
    float al0, al1;
    upk2(av, al0, al1);

    // v = angle from dot axis in [0, pi/2]; th = pi/2 - sign(dot)*v
    const float h0 = PI_2F - al0;
    const float h1 = PI_2F - al1;
    float v0 = (b0 > a0) ? h0 : al0;
    float v1 = (b1 > a1) ? h1 : al1;
    v0 = fminf(v0, VMAX);                              // exact reference clamp
    v1 = fminf(v1, VMAX);
    const float th0 = fmaf(sgn1(c0), -v0, PI_2F);
    const float th1 = fmaf(sgn1(c1), -v1, PI_2F);

    sum0 = fmaf(ftanh(cr0), th0, sum0);                // cr IS K*cross
    sum1 = fmaf(ftanh(cr1), th1, sum1);
}

__global__ void __launch_bounds__(128)
contour_mask_kernel(const float* __restrict__ contour, float* __restrict__ out) {
    // per-edge per-block constants, duplicated into lane pairs, 16B-grouped:
    // s[2j]   = (tK, tK, exK, exK)   tK = K*(w - px*ey), exK = K*ex
    // s[2j+1] = (UK, UK, -sy, -sy)   UK = K*(d + px*(px-sx))
    __shared__ float4 s[2 * NPTS];
    const int t = threadIdx.x;
    const int row = blockIdx.x >> 1;
    const float px = (float)row * (1.0f / (float)MSIZE);

    if (t < NPTS) {
        const float2 c0 = reinterpret_cast<const float2*>(contour)[t];
        const float2 c1 = reinterpret_cast<const float2*>(contour)[(t + 1) & (NPTS - 1)];
        const float w  = fmaf(c0.y, c1.x, -(c0.x * c1.y));
        const float ex = c0.x - c1.x;
        const float ey = c0.y - c1.y;
        const float d  = fmaf(c0.x, c1.x, c0.y * c1.y);
        const float sx = c0.x + c1.x;
        const float sy = c0.y + c1.y;
        const float tK  = KCONST * fmaf(-px, ey, w);
        const float exK = KCONST * ex;
        const float UK  = KCONST * fmaf(px, px - sx, d);
        s[2 * t]     = make_float4(tK, tK, exK, exK);
        s[2 * t + 1] = make_float4(UK, UK, -sy, -sy);
    }
    __syncthreads();

    const int col0 = ((blockIdx.x & 1) << 8) + t;
    const float py0 = (float)col0         * (1.0f / (float)MSIZE);
    const float py1 = (float)(col0 + 128) * (1.0f / (float)MSIZE);
    const u64 pyv  = pk2(py0, py1);
    const u64 Kpyv = pk2(KCONST * py0, KCONST * py1);

    const u64 A9 = A9v, A7 = A7v, A5 = A5v, A3 = A3v, A1 = A1v;

    const ulonglong2* sv = reinterpret_cast<const ulonglong2*>(s);

    // two independent edge streams (j and j+64) -> 4 independent chains
    float sa0 = 0.0f, sa1 = 0.0f, sb0 = 0.0f, sb1 = 0.0f;

#pragma unroll 4
    for (int j = 0; j < HALFE; ++j) {
        const ulonglong2 qa0 = sv[2 * j];
        const ulonglong2 qa1 = sv[2 * j + 1];
        const ulonglong2 qb0 = sv[2 * (j + HALFE)];
        const ulonglong2 qb1 = sv[2 * (j + HALFE) + 1];
        edge_eval(qa0, qa1, pyv, Kpyv, A9, A7, A5, A3, A1, sa0, sa1);
        edge_eval(qb0, qb1, pyv, Kpyv, A9, A7, A5, A3, A1, sb0, sb1);
    }

    const float sum0 = sa0 + sb0;
    const float sum1 = sa1 + sb1;

    const int base = row * MSIZE + col0;
    out[base]       = fminf(fmaxf(sum0 * INV2PI, 0.0f), 1.0f);
    out[base + 128] = fminf(fmaxf(sum1 * INV2PI, 0.0f), 1.0f);
}

extern "C" void kernel_launch(void* const* d_in, const int* in_sizes, int n_in,
                              void* d_out, int out_size) {
    const float* contour = (const float*)d_in[0];
    float* out = (float*)d_out;
    contour_mask_kernel<<<MSIZE * 2, 128>>>(contour, out);
}